// round 5
// baseline (speedup 1.0000x reference)
#include <cuda_runtime.h>
#include <math.h>

constexpr int NB = 128, NA = 2, NH = 128, NW = 128;
constexpr int PLANE = NH * NW;
constexpr float THRESH = 0.6f;
constexpr float OBJ_SCALE = 5.0f;
constexpr float LN_MARGIN = 0.55961579f;   // ln(1.75) > ln(5/3) safety margin
constexpr int NBLOCKS = 4096;              // 1,048,576 threads * 4 cells

// Per-batch constant tables (written by block 0, read by all after flag)
__device__ float4 g_scr[NB * NA];   // lo, hi, aw, ah     (per batch, per anchor)
__device__ float4 g_bb[NB];         // gxm, gxM, gym, gyM (gt box corners)

// Accumulators (zero at module load; reset by last block each run)
__device__ double g_conf2 = 0.0;
__device__ unsigned long long g_cnt = 0ull;
__device__ float  g_sel = 0.0f;
__device__ unsigned g_done = 0u;
__device__ int g_flag = 0;

__device__ __forceinline__ float sig_precise(float x) { return 1.0f / (1.0f + expf(-x)); }
__device__ __forceinline__ float sig_fast(float x) {
    return __fdividef(1.0f, 1.0f + __expf(-x));
}
__device__ __forceinline__ int ld_acq(const int* p) {
    int v; asm volatile("ld.global.acquire.gpu.b32 %0, [%1];" : "=r"(v) : "l"(p) : "memory");
    return v;
}
__device__ __forceinline__ void st_rel(int* p, int v) {
    asm volatile("st.global.release.gpu.b32 [%0], %1;" :: "l"(p), "r"(v) : "memory");
}

__global__ void __launch_bounds__(256) k_fused(const float* __restrict__ out,
                                               const float* __restrict__ tgt,
                                               const float* __restrict__ anc,
                                               float* __restrict__ res) {
    int tid = blockIdx.x * 256 + threadIdx.x;
    int i4 = (tid & 31) * 4;          // 4 consecutive columns
    int r  = tid >> 5;
    int j  = r & 127; r >>= 7;        // row
    int a  = r & 1;                   // anchor (constant per block)
    int b  = r >> 1;                  // batch  (constant per block)

    // ---- issue all 5 streaming loads up-front (MLP=5) ----
    size_t base = ((size_t)(b * 10 + a * 5) * NH + j) * NW + i4;
    float4 vx = *(const float4*)(out + base);
    float4 vy = *(const float4*)(out + base + 1 * (size_t)PLANE);
    float4 vw = *(const float4*)(out + base + 2 * (size_t)PLANE);
    float4 vh = *(const float4*)(out + base + 3 * (size_t)PLANE);
    float4 vc = *(const float4*)(out + base + 4 * (size_t)PLANE);
    // pin the loads before the poll loop
    asm volatile("" :: "f"(vx.x), "f"(vy.x), "f"(vw.x), "f"(vh.x), "f"(vc.x));

    if (blockIdx.x == 0) {
        // ---- device-side init: one thread per batch ----
        int bb = threadIdx.x;
        if (bb < NB) {
            float t0 = tgt[bb*4+0], t1 = tgt[bb*4+1], t2 = tgt[bb*4+2], t3 = tgt[bb*4+3];
            float gx = t0 * (float)NW, gy = t1 * (float)NH;
            float gw = t2 * (float)NW, gh = t3 * (float)NH;
            float a0w = anc[0], a0h = anc[1], a1w = anc[2], a1h = anc[3];

            float ga = gw * gh;
            float i0 = fminf(gw, a0w) * fminf(gh, a0h);
            float u0 = ga + 1e-16f + a0w * a0h - i0;
            float i1 = fminf(gw, a1w) * fminf(gh, a1h);
            float u1 = ga + 1e-16f + a1w * a1h - i1;
            int best = (i1 / u1) > (i0 / u0) ? 1 : 0;

            float gxm = gx - gw * 0.5f, gxM = gx + gw * 0.5f;
            float gym = gy - gh * 0.5f, gyM = gy + gh * 0.5f;
            g_bb[bb] = make_float4(gxm, gxM, gym, gyM);
            float c0 = logf(ga / (a0w * a0h));
            float c1 = logf(ga / (a1w * a1h));
            g_scr[bb*2+0] = make_float4(c0 - LN_MARGIN, c0 + LN_MARGIN, a0w, a0h);
            g_scr[bb*2+1] = make_float4(c1 - LN_MARGIN, c1 + LN_MARGIN, a1w, a1h);

            // excluded cell: exact IoU + conf^2 pre-subtraction + selected loss
            int gxi = (int)gx, gyi = (int)gy;
            const float* p = out + ((size_t)(bb * 10 + best * 5)) * PLANE + gyi * NW + gxi;
            float ox = p[0], oy = p[PLANE], ow = p[2*PLANE], oh = p[3*PLANE], oc = p[4*PLANE];

            float bw = best ? a1w : a0w;
            float bh = best ? a1h : a0h;
            float px = sig_precise(ox) + (float)gxi;
            float py = sig_precise(oy) + (float)gyi;
            float pw = expf(ow) * bw;
            float ph = expf(oh) * bh;
            float mx = fminf(px - pw * 0.5f, gxm);
            float Mx = fmaxf(px + pw * 0.5f, gxM);
            float my = fminf(py - ph * 0.5f, gym);
            float My = fmaxf(py + ph * 0.5f, gyM);
            float cw = pw + gw - (Mx - mx);
            float ch = ph + gh - (My - my);
            float carea = cw * ch;
            float uarea = pw * ph + ga - carea;
            bool cnt_as_noobj = (cw <= 0.0f) || (ch <= 0.0f) || (carea <= THRESH * uarea);
            if (cnt_as_noobj) {
                // k_main will count this cell; reference excludes it -> pre-subtract
                float cs0 = sig_fast(oc);
                atomicAdd(&g_conf2, -(double)(cs0 * cs0));
                atomicAdd(&g_cnt, (unsigned long long)(-1ll));
            }

            float xs = sig_precise(ox), ys = sig_precise(oy), cs = sig_precise(oc);
            float txv = gx - floorf(gx), tyv = gy - floorf(gy);
            float twv = logf(gw / bw + 1e-16f), thv = logf(gh / bh + 1e-16f);
            float sc = 2.0f - t2 * t3;
            float dx = (xs - txv) * sc, dy = (ys - tyv) * sc;
            float dw = (ow - twv) * sc, dh = (oh - thv) * sc;
            float l = dx*dx + dy*dy + dw*dw + dh*dh
                    + OBJ_SCALE * (cs - 1.0f) * (cs - 1.0f);
            atomicAdd(&g_sel, l * (1.0f / (float)NB));
        }
        __syncthreads();
        if (threadIdx.x == 0) {
            __threadfence();
            st_rel(&g_flag, 1);
        }
        // block 0's own threads: constants visible via __syncthreads above
    } else {
        // acquire-poll (overlaps with the 5 loads already in flight)
        if (ld_acq(&g_flag) == 0) {
            while (ld_acq(&g_flag) == 0) { __nanosleep(64); }
        }
    }

    // ---- per (b,a) constants: two broadcast loads ----
    float4 scr = __ldg(&g_scr[b * 2 + a]);   // lo, hi, aw, ah
    float4 bbx = __ldg(&g_bb[b]);            // gxm, gxM, gym, gyM
    float gw = bbx.y - bbx.x;
    float gh = bbx.w - bbx.z;
    float garea = gw * gh;

    float px4[4] = {vx.x, vx.y, vx.z, vx.w};
    float py4[4] = {vy.x, vy.y, vy.z, vy.w};
    float pw4[4] = {vw.x, vw.y, vw.z, vw.w};
    float ph4[4] = {vh.x, vh.y, vh.z, vh.w};
    float pc4[4] = {vc.x, vc.y, vc.z, vc.w};

    float conf2f = 0.0f;
    int cnt = 0;

    #pragma unroll
    for (int k = 0; k < 4; k++) {
        bool noobj = true;
        float s = pw4[k] + ph4[k];
        if ((s > scr.x) && (s < scr.y)) {
            float px = sig_fast(px4[k]) + (float)(i4 + k);
            float py = sig_fast(py4[k]) + (float)j;
            float pw = __expf(pw4[k]) * scr.z;
            float ph = __expf(ph4[k]) * scr.w;
            float mx = fminf(px - pw * 0.5f, bbx.x);
            float Mx = fmaxf(px + pw * 0.5f, bbx.y);
            float my = fminf(py - ph * 0.5f, bbx.z);
            float My = fmaxf(py + ph * 0.5f, bbx.w);
            float cw = pw + gw - (Mx - mx);
            float ch = ph + gh - (My - my);
            float carea = cw * ch;
            float uarea = pw * ph + garea - carea;
            noobj = (cw <= 0.0f) || (ch <= 0.0f) || (carea <= THRESH * uarea);
        }
        if (noobj) {
            float rr = sig_fast(pc4[k]);
            conf2f += rr * rr;
            cnt++;
        }
    }

    // ---- block reduce ----
    #pragma unroll
    for (int o = 16; o > 0; o >>= 1) {
        conf2f += __shfl_down_sync(0xffffffffu, conf2f, o);
        cnt    += __shfl_down_sync(0xffffffffu, cnt, o);
    }
    __shared__ double sh_c2[8];
    __shared__ int    sh_ct[8];
    int lane = threadIdx.x & 31, wrp = threadIdx.x >> 5;
    if (lane == 0) { sh_c2[wrp] = (double)conf2f; sh_ct[wrp] = cnt; }
    __syncthreads();
    if (wrp == 0) {
        double c2 = (lane < 8) ? sh_c2[lane] : 0.0;
        int    ct = (lane < 8) ? sh_ct[lane] : 0;
        #pragma unroll
        for (int o = 4; o > 0; o >>= 1) {
            c2 += __shfl_down_sync(0xffffffffu, c2, o);
            ct += __shfl_down_sync(0xffffffffu, ct, o);
        }
        if (lane == 0) {
            atomicAdd(&g_conf2, c2);
            atomicAdd(&g_cnt, (unsigned long long)ct);
            __threadfence();
            unsigned old = atomicAdd(&g_done, 1u);
            if (old == (unsigned)(NBLOCKS - 1)) {
                __threadfence();
                res[0] = g_sel + (float)((double)g_conf2 / (double)(long long)g_cnt);
                g_conf2 = 0.0; g_cnt = 0ull; g_sel = 0.0f; g_done = 0u;
                g_flag = 0;
            }
        }
    }
}

extern "C" void kernel_launch(void* const* d_in, const int* in_sizes, int n_in,
                              void* d_out, int out_size) {
    const float* out = (const float*)d_in[0];   // (128, 10, 128, 128)
    const float* tgt = (const float*)d_in[1];   // (128, 4)
    const float* anc = (const float*)d_in[2];   // (2, 2)
    float* res = (float*)d_out;

    k_fused<<<NBLOCKS, 256>>>(out, tgt, anc, res);
}

// round 6
// speedup vs baseline: 1.3924x; 1.3924x over previous
#include <cuda_runtime.h>
#include <math.h>

constexpr int NB = 128, NA = 2, NH = 128, NW = 128;
constexpr int PLANE = NH * NW;
constexpr float THRESH = 0.6f;
constexpr float OBJ_SCALE = 5.0f;
constexpr float LN_MARGIN = 0.55961579f;   // ln(1.75) > ln(5/3)+fastlog-err margin
constexpr int NBLOCKS = 4096;              // 1,048,576 threads * 4 cells

// Accumulators (zero at module load; reset by last block each run)
__device__ double g_conf2 = 0.0;
__device__ unsigned long long g_cnt = 0ull;
__device__ float  g_sel = 0.0f;
__device__ unsigned g_done = 0u;

__device__ __forceinline__ float sig_fast(float x) {
    return __fdividef(1.0f, 1.0f + __expf(-x));
}

__global__ void __launch_bounds__(256, 5) k_fused(const float* __restrict__ out,
                                                  const float* __restrict__ tgt,
                                                  const float* __restrict__ anc,
                                                  float* __restrict__ res) {
    int tid = blockIdx.x * 256 + threadIdx.x;
    int i4 = (tid & 31) * 4;          // 4 consecutive columns
    int r  = tid >> 5;
    int j  = r & 127; r >>= 7;        // row
    int a  = r & 1;                   // anchor (block-uniform)
    int b  = r >> 1;                  // batch  (block-uniform)

    // ---- streaming loads first: w, h, conf (always needed) ----
    const float* pbase = out + ((size_t)(b * 10 + a * 5) * NH + j) * NW + i4;
    float4 vw = __ldcs((const float4*)(pbase + 2 * (size_t)PLANE));
    float4 vh = __ldcs((const float4*)(pbase + 3 * (size_t)PLANE));
    float4 vc = __ldcs((const float4*)(pbase + 4 * (size_t)PLANE));

    // ---- per-thread constants (fast math; overlaps in-flight loads) ----
    float4 t = __ldg((const float4*)(tgt + b * 4));     // warp-broadcast
    float gx = t.x * (float)NW, gy = t.y * (float)NH;
    float gw = t.z * (float)NW, gh = t.w * (float)NH;
    float a0w = __ldg(anc + 0), a0h = __ldg(anc + 1);
    float a1w = __ldg(anc + 2), a1h = __ldg(anc + 3);

    float ga = gw * gh;
    float i0 = fminf(gw, a0w) * fminf(gh, a0h);
    float u0 = ga + 1e-16f + a0w * a0h - i0;
    float i1 = fminf(gw, a1w) * fminf(gh, a1h);
    float u1 = ga + 1e-16f + a1w * a1h - i1;
    int best = (i1 * u0 > i0 * u1) ? 1 : 0;             // u0,u1 > 0

    int kx = best * PLANE + (int)gy * NW + (int)gx      // excluded cell
           - (a * PLANE + j * NW + i4);                 // in [0,3] iff owned

    float aw = a ? a1w : a0w;
    float ah = a ? a1h : a0h;
    float cc = __logf(__fdividef(ga, aw * ah));
    float lo = cc - LN_MARGIN, hi = cc + LN_MARGIN;

    float pw4[4] = {vw.x, vw.y, vw.z, vw.w};
    float ph4[4] = {vh.x, vh.y, vh.z, vh.w};
    float pc4[4] = {vc.x, vc.y, vc.z, vc.w};

    bool pass[4];
    bool anyp = false;
    #pragma unroll
    for (int k = 0; k < 4; k++) {
        float s = pw4[k] + ph4[k];
        pass[k] = (s > lo) && (s < hi);
        anyp |= pass[k];
    }
    bool own = (kx >= 0) && (kx < 4);
    bool noobj[4] = {true, true, true, true};
    float selv = 0.0f;

    if (anyp | own) {
        // slow path (~rare): fetch x,y and do the exact IoU
        float4 vx = __ldg((const float4*)(pbase));
        float4 vy = __ldg((const float4*)(pbase + (size_t)PLANE));
        float px4[4] = {vx.x, vx.y, vx.z, vx.w};
        float py4[4] = {vy.x, vy.y, vy.z, vy.w};
        float gxm = gx - gw * 0.5f, gxM = gx + gw * 0.5f;
        float gym = gy - gh * 0.5f, gyM = gy + gh * 0.5f;

        #pragma unroll
        for (int k = 0; k < 4; k++) {          // all compile-time indices
            bool is_excl = (k == kx);
            if (pass[k] | is_excl) {
                float px = sig_fast(px4[k]) + (float)(i4 + k);
                float py = sig_fast(py4[k]) + (float)j;
                float pw = __expf(pw4[k]) * aw;
                float ph = __expf(ph4[k]) * ah;
                float mx = fminf(px - pw * 0.5f, gxm);
                float Mx = fmaxf(px + pw * 0.5f, gxM);
                float my = fminf(py - ph * 0.5f, gym);
                float My = fmaxf(py + ph * 0.5f, gyM);
                float cw = pw + gw - (Mx - mx);
                float ch = ph + gh - (My - my);
                float carea = cw * ch;
                float uarea = pw * ph + ga - carea;
                noobj[k] = (cw <= 0.0f) || (ch <= 0.0f) || (carea <= THRESH * uarea);
                if (is_excl) {
                    noobj[k] = false;
                    float bw = best ? a1w : a0w;
                    float bh = best ? a1h : a0h;
                    float xs = sig_fast(px4[k]);
                    float ys = sig_fast(py4[k]);
                    float cs = sig_fast(pc4[k]);
                    float txv = gx - floorf(gx), tyv = gy - floorf(gy);
                    float twv = __logf(__fdividef(gw, bw) + 1e-16f);
                    float thv = __logf(__fdividef(gh, bh) + 1e-16f);
                    float sc  = 2.0f - t.z * t.w;
                    float dx = (xs - txv) * sc, dy = (ys - tyv) * sc;
                    float dw = (pw4[k] - twv) * sc, dh = (ph4[k] - thv) * sc;
                    selv = (dx*dx + dy*dy + dw*dw + dh*dh
                         + OBJ_SCALE * (cs - 1.0f) * (cs - 1.0f)) * (1.0f / (float)NB);
                }
            }
        }
    }

    float conf2f = 0.0f;
    int cnt = 0;
    #pragma unroll
    for (int k = 0; k < 4; k++) {
        if (noobj[k]) {
            float rr = sig_fast(pc4[k]);
            conf2f += rr * rr;
            cnt++;
        }
    }

    // ---- block reduce (conf2, cnt, selv) ----
    #pragma unroll
    for (int o = 16; o > 0; o >>= 1) {
        conf2f += __shfl_down_sync(0xffffffffu, conf2f, o);
        cnt    += __shfl_down_sync(0xffffffffu, cnt, o);
        selv   += __shfl_down_sync(0xffffffffu, selv, o);
    }
    __shared__ double sh_c2[8];
    __shared__ int    sh_ct[8];
    __shared__ float  sh_sv[8];
    int lane = threadIdx.x & 31, wrp = threadIdx.x >> 5;
    if (lane == 0) { sh_c2[wrp] = (double)conf2f; sh_ct[wrp] = cnt; sh_sv[wrp] = selv; }
    __syncthreads();
    if (wrp == 0) {
        double c2 = (lane < 8) ? sh_c2[lane] : 0.0;
        int    ct = (lane < 8) ? sh_ct[lane] : 0;
        float  sv = (lane < 8) ? sh_sv[lane] : 0.0f;
        #pragma unroll
        for (int o = 4; o > 0; o >>= 1) {
            c2 += __shfl_down_sync(0xffffffffu, c2, o);
            ct += __shfl_down_sync(0xffffffffu, ct, o);
            sv += __shfl_down_sync(0xffffffffu, sv, o);
        }
        if (lane == 0) {
            atomicAdd(&g_conf2, c2);
            atomicAdd(&g_cnt, (unsigned long long)ct);
            if (sv != 0.0f) atomicAdd(&g_sel, sv);
            __threadfence();
            unsigned old = atomicAdd(&g_done, 1u);
            if (old == (unsigned)(NBLOCKS - 1)) {
                __threadfence();
                res[0] = g_sel + (float)(g_conf2 / (double)g_cnt);
                g_conf2 = 0.0; g_cnt = 0ull; g_sel = 0.0f; g_done = 0u;
            }
        }
    }
}

extern "C" void kernel_launch(void* const* d_in, const int* in_sizes, int n_in,
                              void* d_out, int out_size) {
    const float* out = (const float*)d_in[0];   // (128, 10, 128, 128)
    const float* tgt = (const float*)d_in[1];   // (128, 4)
    const float* anc = (const float*)d_in[2];   // (2, 2)
    float* res = (float*)d_out;

    k_fused<<<NBLOCKS, 256>>>(out, tgt, anc, res);
}

// round 7
// speedup vs baseline: 1.5405x; 1.1064x over previous
#include <cuda_runtime.h>
#include <math.h>

constexpr int NB = 128, NA = 2, NH = 128, NW = 128;
constexpr int PLANE = NH * NW;
constexpr float THRESH = 0.6f;
constexpr float OBJ_SCALE = 5.0f;
constexpr float LN_MARGIN = 0.55961579f;   // ln(1.75) > ln(5/3)+fastlog-err margin
constexpr int NBLOCKS = 2048;              // 524288 threads * 8 cells

// Accumulators (zero at module load; reset by last block each run)
__device__ double g_conf2 = 0.0;
__device__ unsigned long long g_cnt = 0ull;
__device__ float  g_sel = 0.0f;
__device__ unsigned g_done = 0u;

__device__ __forceinline__ float sig_fast(float x) {
    return __fdividef(1.0f, 1.0f + __expf(-x));
}

// Process one 4-cell chunk. All loop indices compile-time after unroll.
__device__ __forceinline__ void process4(
    float4 vw, float4 vh, float4 vc,
    const float* pbase,                 // points at (b,a,plane0,j,icol)
    int icol, int j, int kx,            // kx in [0,3] iff this chunk owns excl cell
    float lo, float hi, float aw, float ah,
    float gx, float gy, float gw, float gh, float ga,
    float bw, float bh, float tscale,
    float& conf2f, int& cnt, float& selv)
{
    float pw4[4] = {vw.x, vw.y, vw.z, vw.w};
    float ph4[4] = {vh.x, vh.y, vh.z, vh.w};
    float pc4[4] = {vc.x, vc.y, vc.z, vc.w};

    bool pass[4];
    bool anyp = false;
    #pragma unroll
    for (int k = 0; k < 4; k++) {
        float s = pw4[k] + ph4[k];
        pass[k] = (s > lo) && (s < hi);
        anyp |= pass[k];
    }
    bool own = (kx >= 0) && (kx < 4);
    bool noobj[4] = {true, true, true, true};

    if (anyp | own) {
        float4 vx = __ldg((const float4*)(pbase));
        float4 vy = __ldg((const float4*)(pbase + (size_t)PLANE));
        float px4[4] = {vx.x, vx.y, vx.z, vx.w};
        float py4[4] = {vy.x, vy.y, vy.z, vy.w};
        float gxm = gx - gw * 0.5f, gxM = gx + gw * 0.5f;
        float gym = gy - gh * 0.5f, gyM = gy + gh * 0.5f;

        #pragma unroll
        for (int k = 0; k < 4; k++) {
            bool is_excl = (k == kx);
            if (pass[k] | is_excl) {
                float px = sig_fast(px4[k]) + (float)(icol + k);
                float py = sig_fast(py4[k]) + (float)j;
                float pw = __expf(pw4[k]) * aw;
                float ph = __expf(ph4[k]) * ah;
                float mx = fminf(px - pw * 0.5f, gxm);
                float Mx = fmaxf(px + pw * 0.5f, gxM);
                float my = fminf(py - ph * 0.5f, gym);
                float My = fmaxf(py + ph * 0.5f, gyM);
                float cw = pw + gw - (Mx - mx);
                float ch = ph + gh - (My - my);
                float carea = cw * ch;
                float uarea = pw * ph + ga - carea;
                noobj[k] = (cw <= 0.0f) || (ch <= 0.0f) || (carea <= THRESH * uarea);
                if (is_excl) {
                    noobj[k] = false;
                    float xs = sig_fast(px4[k]);
                    float ys = sig_fast(py4[k]);
                    float cs = sig_fast(pc4[k]);
                    float txv = gx - floorf(gx), tyv = gy - floorf(gy);
                    float twv = __logf(__fdividef(gw, bw) + 1e-16f);
                    float thv = __logf(__fdividef(gh, bh) + 1e-16f);
                    float dx = (xs - txv) * tscale, dy = (ys - tyv) * tscale;
                    float dw = (pw4[k] - twv) * tscale, dh = (ph4[k] - thv) * tscale;
                    selv += (dx*dx + dy*dy + dw*dw + dh*dh
                          + OBJ_SCALE * (cs - 1.0f) * (cs - 1.0f)) * (1.0f / (float)NB);
                }
            }
        }
    }

    #pragma unroll
    for (int k = 0; k < 4; k++) {
        if (noobj[k]) {
            float rr = sig_fast(pc4[k]);
            conf2f += rr * rr;
            cnt++;
        }
    }
}

__global__ void __launch_bounds__(256) k_fused(const float* __restrict__ out,
                                               const float* __restrict__ tgt,
                                               const float* __restrict__ anc,
                                               float* __restrict__ res) {
    int tid = blockIdx.x * 256 + threadIdx.x;
    int i4 = (tid & 15) * 4;          // chunk A cols [i4, i4+4); chunk B +64
    int r  = tid >> 4;
    int j  = r & 127; r >>= 7;        // row
    int a  = r & 1;                   // anchor (block-uniform)
    int b  = r >> 1;                  // batch  (block-uniform)

    // ---- 6 front-batched streaming loads: w,h,conf for both chunks ----
    const float* pbase = out + ((size_t)(b * 10 + a * 5) * NH + j) * NW + i4;
    float4 wA = *(const float4*)(pbase + 2 * (size_t)PLANE);
    float4 wB = *(const float4*)(pbase + 2 * (size_t)PLANE + 64);
    float4 hA = *(const float4*)(pbase + 3 * (size_t)PLANE);
    float4 hB = *(const float4*)(pbase + 3 * (size_t)PLANE + 64);
    float4 cA = *(const float4*)(pbase + 4 * (size_t)PLANE);
    float4 cB = *(const float4*)(pbase + 4 * (size_t)PLANE + 64);

    // ---- per-thread constants (overlap the in-flight loads) ----
    float4 t = __ldg((const float4*)(tgt + b * 4));     // warp-broadcast
    float gx = t.x * (float)NW, gy = t.y * (float)NH;
    float gw = t.z * (float)NW, gh = t.w * (float)NH;
    float a0w = __ldg(anc + 0), a0h = __ldg(anc + 1);
    float a1w = __ldg(anc + 2), a1h = __ldg(anc + 3);

    float ga = gw * gh;
    float i0 = fminf(gw, a0w) * fminf(gh, a0h);
    float u0 = ga + 1e-16f + a0w * a0h - i0;
    float i1 = fminf(gw, a1w) * fminf(gh, a1h);
    float u1 = ga + 1e-16f + a1w * a1h - i1;
    int best = (i1 * u0 > i0 * u1) ? 1 : 0;             // u0,u1 > 0

    int excl = best * PLANE + (int)gy * NW + (int)gx;
    int lbase = a * PLANE + j * NW + i4;
    int kxA = excl - lbase;           // in [0,3] iff chunk A owns it
    int kxB = excl - lbase - 64;      // in [0,3] iff chunk B owns it

    float aw = a ? a1w : a0w;
    float ah = a ? a1h : a0h;
    float cc = __logf(__fdividef(ga, aw * ah));
    float lo = cc - LN_MARGIN, hi = cc + LN_MARGIN;
    float bw = best ? a1w : a0w;
    float bh = best ? a1h : a0h;
    float tscale = 2.0f - t.z * t.w;

    float conf2f = 0.0f;
    float selv = 0.0f;
    int cnt = 0;

    process4(wA, hA, cA, pbase,      i4,      j, kxA, lo, hi, aw, ah,
             gx, gy, gw, gh, ga, bw, bh, tscale, conf2f, cnt, selv);
    process4(wB, hB, cB, pbase + 64, i4 + 64, j, kxB, lo, hi, aw, ah,
             gx, gy, gw, gh, ga, bw, bh, tscale, conf2f, cnt, selv);

    // ---- block reduce (conf2, cnt, selv) ----
    #pragma unroll
    for (int o = 16; o > 0; o >>= 1) {
        conf2f += __shfl_down_sync(0xffffffffu, conf2f, o);
        cnt    += __shfl_down_sync(0xffffffffu, cnt, o);
        selv   += __shfl_down_sync(0xffffffffu, selv, o);
    }
    __shared__ double sh_c2[8];
    __shared__ int    sh_ct[8];
    __shared__ float  sh_sv[8];
    int lane = threadIdx.x & 31, wrp = threadIdx.x >> 5;
    if (lane == 0) { sh_c2[wrp] = (double)conf2f; sh_ct[wrp] = cnt; sh_sv[wrp] = selv; }
    __syncthreads();
    if (wrp == 0) {
        double c2 = (lane < 8) ? sh_c2[lane] : 0.0;
        int    ct = (lane < 8) ? sh_ct[lane] : 0;
        float  sv = (lane < 8) ? sh_sv[lane] : 0.0f;
        #pragma unroll
        for (int o = 4; o > 0; o >>= 1) {
            c2 += __shfl_down_sync(0xffffffffu, c2, o);
            ct += __shfl_down_sync(0xffffffffu, ct, o);
            sv += __shfl_down_sync(0xffffffffu, sv, o);
        }
        if (lane == 0) {
            atomicAdd(&g_conf2, c2);
            atomicAdd(&g_cnt, (unsigned long long)ct);
            if (sv != 0.0f) atomicAdd(&g_sel, sv);
            __threadfence();
            unsigned old = atomicAdd(&g_done, 1u);
            if (old == (unsigned)(NBLOCKS - 1)) {
                __threadfence();
                res[0] = g_sel + (float)(g_conf2 / (double)g_cnt);
                g_conf2 = 0.0; g_cnt = 0ull; g_sel = 0.0f; g_done = 0u;
            }
        }
    }
}

extern "C" void kernel_launch(void* const* d_in, const int* in_sizes, int n_in,
                              void* d_out, int out_size) {
    const float* out = (const float*)d_in[0];   // (128, 10, 128, 128)
    const float* tgt = (const float*)d_in[1];   // (128, 4)
    const float* anc = (const float*)d_in[2];   // (2, 2)
    float* res = (float*)d_out;

    k_fused<<<NBLOCKS, 256>>>(out, tgt, anc, res);
}